// round 2
// baseline (speedup 1.0000x reference)
#include <cuda_runtime.h>

#define BATCH 4
#define CH 256
#define NQ 4096        /* 64*64 query tokens per batch  */
#define NK 4356        /* 66*66 key tokens per batch    */
#define BN_EPS 1e-5f
#define NEG_INF (-1e30f)

// ---------------- scratch (no allocations allowed) ----------------
__device__ float g_Qraw[BATCH * CH * NQ];   // conv3x3 output (pre-BN)
__device__ float g_Kraw[BATCH * CH * NK];   // conv1x1 output incl. padded border (pre-BN)
__device__ float g_Vraw[BATCH * CH * NK];
__device__ float g_aff[6 * CH];             // aQ,bQ,aK,bK,aV,bV  (BN folded to affine)

// =================================================================
// conv3x3 as implicit GEMM: out[oc][p] = sum_{ic,kh,kw} W * x, per batch.
// Block: 64 oc x 64 pixels (one image row), K-chunks of 32.
// =================================================================
__global__ __launch_bounds__(256)
void conv3x3_kernel(const float* __restrict__ x, const float* __restrict__ W,
                    const float* __restrict__ bias)
{
    __shared__ float sA[32][68];   // [krow][oc]  (transposed weights)
    __shared__ float sB[32][68];   // [krow][pixel] (im2col)
    const int tid = threadIdx.x;
    const int oc0 = blockIdx.x * 64;
    const int h   = blockIdx.y;
    const int b   = blockIdx.z;
    const int to = tid & 15;       // oc quad
    const int tp = tid >> 4;       // pixel quad
    const int ocl = tid >> 2;      // A-load: oc lane
    const int rb  = (tid & 3) * 8; // A-load: krow base
    const int rB  = tid >> 3;      // B-load: krow
    const int wg  = tid & 7;       // B-load: w group
    const float* xb = x + (size_t)b * CH * NQ;

    float acc[4][4];
#pragma unroll
    for (int i = 0; i < 4; ++i)
#pragma unroll
        for (int j = 0; j < 4; ++j) acc[i][j] = 0.f;

    for (int kc = 0; kc < 2304; kc += 32) {
        // ---- load A tile (weights, transposed) ----
        const float* wsrc = W + (size_t)(oc0 + ocl) * 2304 + kc + rb;
        float4 w0 = *(const float4*)wsrc;
        float4 w1 = *(const float4*)(wsrc + 4);
        sA[rb+0][ocl] = w0.x; sA[rb+1][ocl] = w0.y; sA[rb+2][ocl] = w0.z; sA[rb+3][ocl] = w0.w;
        sA[rb+4][ocl] = w1.x; sA[rb+5][ocl] = w1.y; sA[rb+6][ocl] = w1.z; sA[rb+7][ocl] = w1.w;

        // ---- load B tile (im2col on the fly; h fixed per block) ----
        {
            int kr = kc + rB;
            int ic = kr / 9;
            int t9 = kr - ic * 9;
            int kh = t9 / 3;
            int kw = t9 - kh * 3;
            int hh = h + kh - 1;
            bool vh = ((unsigned)hh < 64u);
            const float* rowp = xb + ((size_t)ic * 64 + hh) * 64 + (kw - 1);
#pragma unroll
            for (int i = 0; i < 8; ++i) {
                int w_ = wg + i * 8;
                float v = 0.f;
                if (vh && (unsigned)(w_ + kw - 1) < 64u) v = rowp[w_];
                sB[rB][w_] = v;
            }
        }
        __syncthreads();

#pragma unroll 8
        for (int cc = 0; cc < 32; ++cc) {
            float4 a4 = *(const float4*)&sA[cc][to * 4];
            float4 b4 = *(const float4*)&sB[cc][tp * 4];
            float av[4] = {a4.x, a4.y, a4.z, a4.w};
            float bv[4] = {b4.x, b4.y, b4.z, b4.w};
#pragma unroll
            for (int i = 0; i < 4; ++i)
#pragma unroll
                for (int j = 0; j < 4; ++j)
                    acc[i][j] = fmaf(av[i], bv[j], acc[i][j]);
        }
        __syncthreads();
    }

#pragma unroll
    for (int i = 0; i < 4; ++i) {
        int oc = oc0 + to * 4 + i;
        float bs = bias[oc];
        float4 o = make_float4(acc[i][0] + bs, acc[i][1] + bs,
                               acc[i][2] + bs, acc[i][3] + bs);
        *(float4*)(g_Qraw + ((size_t)(b * CH + oc)) * NQ + h * 64 + tp * 4) = o;
    }
}

// =================================================================
// conv1x1 for K and V fused (x tile shared). Writes interior of the
// 66x66 padded grid; h==0 blocks also fill the bias-only border.
// =================================================================
__global__ __launch_bounds__(256)
void conv1x1_kernel(const float* __restrict__ x,
                    const float* __restrict__ Wk, const float* __restrict__ Wv,
                    const float* __restrict__ bk, const float* __restrict__ bv)
{
    __shared__ float sAk[32][68], sAv[32][68], sX[32][68];
    const int tid = threadIdx.x;
    const int oc0 = blockIdx.x * 64;
    const int h   = blockIdx.y;
    const int b   = blockIdx.z;
    const int to = tid & 15;
    const int tp = tid >> 4;
    const int ocl = tid >> 2;
    const int rb  = (tid & 3) * 8;
    const int rX  = tid >> 3;
    const int wgx = (tid & 7) * 8;

    float ak[4][4], av2[4][4];
#pragma unroll
    for (int i = 0; i < 4; ++i)
#pragma unroll
        for (int j = 0; j < 4; ++j) { ak[i][j] = 0.f; av2[i][j] = 0.f; }

    for (int kc = 0; kc < 256; kc += 32) {
        const float* wks = Wk + (size_t)(oc0 + ocl) * 256 + kc + rb;
        const float* wvs = Wv + (size_t)(oc0 + ocl) * 256 + kc + rb;
        float4 a0 = *(const float4*)wks;
        float4 a1 = *(const float4*)(wks + 4);
        sAk[rb+0][ocl] = a0.x; sAk[rb+1][ocl] = a0.y; sAk[rb+2][ocl] = a0.z; sAk[rb+3][ocl] = a0.w;
        sAk[rb+4][ocl] = a1.x; sAk[rb+5][ocl] = a1.y; sAk[rb+6][ocl] = a1.z; sAk[rb+7][ocl] = a1.w;
        float4 c0 = *(const float4*)wvs;
        float4 c1 = *(const float4*)(wvs + 4);
        sAv[rb+0][ocl] = c0.x; sAv[rb+1][ocl] = c0.y; sAv[rb+2][ocl] = c0.z; sAv[rb+3][ocl] = c0.w;
        sAv[rb+4][ocl] = c1.x; sAv[rb+5][ocl] = c1.y; sAv[rb+6][ocl] = c1.z; sAv[rb+7][ocl] = c1.w;

        const float* xs = x + ((size_t)(b * CH + kc + rX) * 64 + h) * 64 + wgx;
        float4 x0 = *(const float4*)xs;
        float4 x1 = *(const float4*)(xs + 4);
        *(float4*)&sX[rX][wgx]     = x0;
        *(float4*)&sX[rX][wgx + 4] = x1;
        __syncthreads();

#pragma unroll 8
        for (int cc = 0; cc < 32; ++cc) {
            float4 ka = *(const float4*)&sAk[cc][to * 4];
            float4 va = *(const float4*)&sAv[cc][to * 4];
            float4 xq = *(const float4*)&sX[cc][tp * 4];
            float kr[4] = {ka.x, ka.y, ka.z, ka.w};
            float vr[4] = {va.x, va.y, va.z, va.w};
            float xr[4] = {xq.x, xq.y, xq.z, xq.w};
#pragma unroll
            for (int i = 0; i < 4; ++i)
#pragma unroll
                for (int j = 0; j < 4; ++j) {
                    ak[i][j]  = fmaf(kr[i], xr[j], ak[i][j]);
                    av2[i][j] = fmaf(vr[i], xr[j], av2[i][j]);
                }
        }
        __syncthreads();
    }

    size_t tokbase = (size_t)(h + 1) * 66 + 1 + tp * 4;
#pragma unroll
    for (int i = 0; i < 4; ++i) {
        int oc = oc0 + to * 4 + i;
        float bks = bk[oc], bvs = bv[oc];
        size_t base = ((size_t)(b * CH + oc)) * NK + tokbase;
#pragma unroll
        for (int j = 0; j < 4; ++j) {
            g_Kraw[base + j] = ak[i][j] + bks;
            g_Vraw[base + j] = av2[i][j] + bvs;
        }
    }

    // ---- border fill (bias only): h==0 blocks handle their 64 oc ----
    if (h == 0) {
        // 64 oc x 260 border elems = 16640; 256 threads -> 65 each
        for (int e = tid; e < 64 * 260; e += 256) {
            int oc = oc0 + (e / 260);
            int p  = e % 260;
            int i2, j2;
            if (p < 66)       { i2 = 0;       j2 = p;       }
            else if (p < 132) { i2 = 65;      j2 = p - 66;  }
            else if (p < 196) { i2 = p - 131; j2 = 0;       }
            else              { i2 = p - 195; j2 = 65;      }
            size_t off = ((size_t)(b * CH + oc)) * NK + i2 * 66 + j2;
            g_Kraw[off] = bk[oc];
            g_Vraw[off] = bv[oc];
        }
    }
}

// =================================================================
// BatchNorm statistics -> per-channel affine (a*x + b).
// blockIdx.y selects tensor (0=Q,1=K,2=V). float4 main loop + scalar tail.
// =================================================================
__global__ __launch_bounds__(256)
void bn_stats_kernel(const float* __restrict__ gq, const float* __restrict__ betaq,
                     const float* __restrict__ gk, const float* __restrict__ betak,
                     const float* __restrict__ gv, const float* __restrict__ betav)
{
    const int which = blockIdx.y;
    const float* data  = (which == 0) ? g_Qraw : (which == 1 ? g_Kraw : g_Vraw);
    const float* gamma = (which == 0) ? gq : (which == 1 ? gk : gv);
    const float* beta  = (which == 0) ? betaq : (which == 1 ? betak : betav);
    const int T = (which == 0) ? NQ : NK;
    const int c = blockIdx.x;
    const int tid = threadIdx.x;
    __shared__ float rs[256], rq[256];
    float s = 0.f, s2 = 0.f;
    const int T4 = T & ~3;
    for (int b = 0; b < BATCH; ++b) {
        const float* p = data + ((size_t)(b * CH + c)) * T;
        for (int i = tid * 4; i < T4; i += 1024) {
            float4 v = *(const float4*)(p + i);
            s += v.x + v.y + v.z + v.w;
            s2 = fmaf(v.x, v.x, s2); s2 = fmaf(v.y, v.y, s2);
            s2 = fmaf(v.z, v.z, s2); s2 = fmaf(v.w, v.w, s2);
        }
        for (int i = T4 + tid; i < T; i += 256) {
            float v = p[i];
            s += v;
            s2 = fmaf(v, v, s2);
        }
    }
    rs[tid] = s; rq[tid] = s2;
    __syncthreads();
    for (int off = 128; off > 0; off >>= 1) {
        if (tid < off) { rs[tid] += rs[tid + off]; rq[tid] += rq[tid + off]; }
        __syncthreads();
    }
    if (tid == 0) {
        float n = (float)(BATCH * T);
        float mean = rs[0] / n;
        float var = rq[0] / n - mean * mean;
        if (var < 0.f) var = 0.f;
        float a = gamma[c] * rsqrtf(var + BN_EPS);
        g_aff[(2 * which)     * CH + c] = a;
        g_aff[(2 * which + 1) * CH + c] = beta[c] - mean * a;
    }
}

// =================================================================
// Flash attention over channels: out[c,q] = sum_k V[c,k] softmax_k(K^T Q)
// Block = (batch, 64-query tile); streams 64-key tiles; BN affine applied
// on smem load; 256x64 fp32 accumulator in registers (8c x 4q per thread).
// =================================================================
struct FlashSmem {
    float sQ[CH][64];     // [c][q]
    float sK[CH][64];     // [c][k]
    float sV[64][260];    // [k][c] (transposed, +4 pad)
    float sS[64][68];     // [k][q] scores -> probs (+4 pad)
    float aff[6][CH];
    float m[64];
    float l[64];
    float r[64];
    float pm[8][64];
    float ps[8][64];
};

__global__ __launch_bounds__(512, 1)
void flash_attn_kernel(float* __restrict__ out)
{
    extern __shared__ char smem_raw[];
    FlashSmem* S = reinterpret_cast<FlashSmem*>(smem_raw);
    const int tid = threadIdx.x;
    const int b  = blockIdx.y;
    const int q0 = blockIdx.x * 64;

    if (tid < CH) {
#pragma unroll
        for (int j = 0; j < 6; ++j) S->aff[j][tid] = g_aff[j * CH + tid];
    }
    if (tid < 64) { S->m[tid] = NEG_INF; S->l[tid] = 0.f; }
    __syncthreads();

    // ---- load Q tile with BN affine ----
    {
        const int c = tid >> 1, half = tid & 1;
        const float a = S->aff[0][c], s = S->aff[1][c];
        const float* src = g_Qraw + ((size_t)(b * CH + c)) * NQ + q0 + half * 32;
        float* dst = &S->sQ[c][half * 32];
#pragma unroll
        for (int i = 0; i < 8; ++i) {
            float4 v = *(const float4*)(src + i * 4);
            v.x = fmaf(a, v.x, s); v.y = fmaf(a, v.y, s);
            v.z = fmaf(a, v.z, s); v.w = fmaf(a, v.w, s);
            *(float4*)(dst + i * 4) = v;
        }
    }

    const int tk  = tid & 31;          // GEMM1 key pair
    const int tq4 = (tid >> 5) * 4;    // query quad (both GEMMs)
    const int c8  = (tid & 31) * 8;    // GEMM2 channel octet
    const int qs  = tid & 63;          // softmax column
    const int seg = tid >> 6;          // softmax row segment

    float acc[8][4];
#pragma unroll
    for (int i = 0; i < 8; ++i)
#pragma unroll
        for (int j = 0; j < 4; ++j) acc[i][j] = 0.f;

    __syncthreads();

    for (int k0 = 0; k0 < NK; k0 += 64) {
        // ---- load K/V tiles (affine applied; V transposed) ----
        {
            const int c = tid >> 1, half = tid & 1;
            const float akf = S->aff[2][c], bkf = S->aff[3][c];
            const float avf = S->aff[4][c], bvf = S->aff[5][c];
            const float* ksrc = g_Kraw + ((size_t)(b * CH + c)) * NK;
            const float* vsrc = g_Vraw + ((size_t)(b * CH + c)) * NK;
#pragma unroll
            for (int i = 0; i < 8; ++i) {
                int kk = half * 32 + i * 4;
                int g = k0 + kk;
                if (g > NK - 4) g = NK - 4;      // clamp; tail masked in softmax
                float4 kv = *(const float4*)(ksrc + g);
                kv.x = fmaf(akf, kv.x, bkf); kv.y = fmaf(akf, kv.y, bkf);
                kv.z = fmaf(akf, kv.z, bkf); kv.w = fmaf(akf, kv.w, bkf);
                *(float4*)&S->sK[c][kk] = kv;
                float4 vv = *(const float4*)(vsrc + g);
                vv.x = fmaf(avf, vv.x, bvf); vv.y = fmaf(avf, vv.y, bvf);
                vv.z = fmaf(avf, vv.z, bvf); vv.w = fmaf(avf, vv.w, bvf);
                S->sV[kk + 0][c] = vv.x; S->sV[kk + 1][c] = vv.y;
                S->sV[kk + 2][c] = vv.z; S->sV[kk + 3][c] = vv.w;
            }
        }
        __syncthreads();

        // ---- GEMM1: scores[k][q] = sum_c K[c][k] * Q[c][q] ----
        {
            float sc[2][4];
#pragma unroll
            for (int i = 0; i < 2; ++i)
#pragma unroll
                for (int j = 0; j < 4; ++j) sc[i][j] = 0.f;
#pragma unroll 8
            for (int c2 = 0; c2 < CH; ++c2) {
                float2 kf = *(const float2*)&S->sK[c2][tk * 2];
                float4 qf = *(const float4*)&S->sQ[c2][tq4];
                float qr[4] = {qf.x, qf.y, qf.z, qf.w};
#pragma unroll
                for (int j = 0; j < 4; ++j) {
                    sc[0][j] = fmaf(kf.x, qr[j], sc[0][j]);
                    sc[1][j] = fmaf(kf.y, qr[j], sc[1][j]);
                }
            }
#pragma unroll
            for (int i = 0; i < 2; ++i)
#pragma unroll
                for (int j = 0; j < 4; ++j)
                    S->sS[tk * 2 + i][tq4 + j] = sc[i][j];
        }
        __syncthreads();

        // ---- online softmax over key dim ----
        int kvalid = NK - k0; if (kvalid > 64) kvalid = 64;
        {
            float pmx = NEG_INF;
#pragma unroll
            for (int rr = 0; rr < 8; ++rr) {
                int row = seg * 8 + rr;
                if (row < kvalid) pmx = fmaxf(pmx, S->sS[row][qs]);
            }
            S->pm[seg][qs] = pmx;
        }
        __syncthreads();
        if (tid < 64) {
            float mold = S->m[tid];
            float mx = mold;
#pragma unroll
            for (int s2 = 0; s2 < 8; ++s2) mx = fmaxf(mx, S->pm[s2][tid]);
            S->m[tid] = mx;
            S->r[tid] = __expf(mold - mx);
        }
        __syncthreads();
        {
            const float mq = S->m[qs];
            float psum = 0.f;
#pragma unroll
            for (int rr = 0; rr < 8; ++rr) {
                int row = seg * 8 + rr;
                float e = 0.f;
                if (row < kvalid) e = __expf(S->sS[row][qs] - mq);
                S->sS[row][qs] = e;
                psum += e;
            }
            S->ps[seg][qs] = psum;
        }
        __syncthreads();
        if (tid < 64) {
            float lv = S->l[tid] * S->r[tid];
#pragma unroll
            for (int s2 = 0; s2 < 8; ++s2) lv += S->ps[s2][tid];
            S->l[tid] = lv;
        }

        // ---- GEMM2: acc[c][q] = acc*r + sum_k V[c][k] P[k][q] ----
        {
            float rj[4];
#pragma unroll
            for (int j = 0; j < 4; ++j) rj[j] = S->r[tq4 + j];
#pragma unroll
            for (int i = 0; i < 8; ++i)
#pragma unroll
                for (int j = 0; j < 4; ++j) acc[i][j] *= rj[j];
#pragma unroll 8
            for (int kk = 0; kk < 64; ++kk) {
                float4 p  = *(const float4*)&S->sS[kk][tq4];
                float4 v0 = *(const float4*)&S->sV[kk][c8];
                float4 v1 = *(const float4*)&S->sV[kk][c8 + 4];
                float pj[4] = {p.x, p.y, p.z, p.w};
                float vi[8] = {v0.x, v0.y, v0.z, v0.w, v1.x, v1.y, v1.z, v1.w};
#pragma unroll
                for (int i = 0; i < 8; ++i)
#pragma unroll
                    for (int j = 0; j < 4; ++j)
                        acc[i][j] = fmaf(vi[i], pj[j], acc[i][j]);
            }
        }
        __syncthreads();
    }

    // ---- epilogue: divide by softmax denominator ----
    float linv[4];
#pragma unroll
    for (int j = 0; j < 4; ++j) linv[j] = 1.f / S->l[tq4 + j];
#pragma unroll
    for (int i = 0; i < 8; ++i) {
        float4 o;
        o.x = acc[i][0] * linv[0]; o.y = acc[i][1] * linv[1];
        o.z = acc[i][2] * linv[2]; o.w = acc[i][3] * linv[3];
        *(float4*)(out + ((size_t)(b * CH + c8 + i)) * NQ + q0 + tq4) = o;
    }
}

// =================================================================
extern "C" void kernel_launch(void* const* d_in, const int* in_sizes, int n_in,
                              void* d_out, int out_size)
{
    (void)in_sizes; (void)n_in; (void)out_size;
    const float* x     = (const float*)d_in[0];
    const float* Wq    = (const float*)d_in[1];
    const float* bq    = (const float*)d_in[2];
    const float* gq    = (const float*)d_in[3];
    const float* betaq = (const float*)d_in[4];
    const float* Wk    = (const float*)d_in[5];
    const float* bk    = (const float*)d_in[6];
    const float* gk    = (const float*)d_in[7];
    const float* betak = (const float*)d_in[8];
    const float* Wv    = (const float*)d_in[9];
    const float* bv    = (const float*)d_in[10];
    const float* gv    = (const float*)d_in[11];
    const float* betav = (const float*)d_in[12];
    float* out = (float*)d_out;

    conv3x3_kernel<<<dim3(4, 64, BATCH), 256>>>(x, Wq, bq);
    conv1x1_kernel<<<dim3(4, 64, BATCH), 256>>>(x, Wk, Wv, bk, bv);
    bn_stats_kernel<<<dim3(CH, 3), 256>>>(gq, betaq, gk, betak, gv, betav);

    cudaFuncSetAttribute(flash_attn_kernel,
                         cudaFuncAttributeMaxDynamicSharedMemorySize,
                         (int)sizeof(FlashSmem));
    flash_attn_kernel<<<dim3(NQ / 64, BATCH), 512, sizeof(FlashSmem)>>>(out);
}

// round 6
// speedup vs baseline: 1.8695x; 1.8695x over previous
#include <cuda_runtime.h>
#include <cuda_bf16.h>
#include <cuda_fp16.h>
#include <cstdint>

#define BATCH 4
#define CH 256
#define NQ 4096        /* 64*64 query tokens per batch  */
#define NK 4356        /* 66*66 key tokens per batch    */
#define NKT 69         /* key tiles of 64 (padded 4416) */
#define NKP (NKT * 64)
#define BN_EPS 1e-5f

// ---------------- scratch (no allocations allowed) ----------------
__device__ float g_Qraw[BATCH * CH * NQ];
__device__ float g_Kraw[BATCH * CH * NK];
__device__ float g_Vraw[BATCH * CH * NK];
__device__ float g_aff[6 * CH];             // aQ,bQ,aK,bK,aV,bV
// converted operands
__device__ __nv_bfloat16 g_Qh[BATCH * NQ * CH];      // [b][q][c]
__device__ __nv_bfloat16 g_Ql[BATCH * NQ * CH];
__device__ __nv_bfloat16 g_Kh[BATCH * NKP * CH];     // [b][tok][c] (zero-padded tail)
__device__ __nv_bfloat16 g_Kl[BATCH * NKP * CH];
__device__ __half        g_Vh[BATCH * NKT * 256 * 64]; // [b][t][c][k]
__device__ __half        g_Vl[BATCH * NKT * 256 * 64];

// =================================================================
// conv3x3 implicit GEMM (unchanged from passing R2 kernel)
// =================================================================
__global__ __launch_bounds__(256)
void conv3x3_kernel(const float* __restrict__ x, const float* __restrict__ W,
                    const float* __restrict__ bias)
{
    __shared__ float sA[32][68];
    __shared__ float sB[32][68];
    const int tid = threadIdx.x;
    const int oc0 = blockIdx.x * 64;
    const int h   = blockIdx.y;
    const int b   = blockIdx.z;
    const int to = tid & 15;
    const int tp = tid >> 4;
    const int ocl = tid >> 2;
    const int rb  = (tid & 3) * 8;
    const int rB  = tid >> 3;
    const int wg  = tid & 7;
    const float* xb = x + (size_t)b * CH * NQ;

    float acc[4][4];
#pragma unroll
    for (int i = 0; i < 4; ++i)
#pragma unroll
        for (int j = 0; j < 4; ++j) acc[i][j] = 0.f;

    for (int kc = 0; kc < 2304; kc += 32) {
        const float* wsrc = W + (size_t)(oc0 + ocl) * 2304 + kc + rb;
        float4 w0 = *(const float4*)wsrc;
        float4 w1 = *(const float4*)(wsrc + 4);
        sA[rb+0][ocl] = w0.x; sA[rb+1][ocl] = w0.y; sA[rb+2][ocl] = w0.z; sA[rb+3][ocl] = w0.w;
        sA[rb+4][ocl] = w1.x; sA[rb+5][ocl] = w1.y; sA[rb+6][ocl] = w1.z; sA[rb+7][ocl] = w1.w;
        {
            int kr = kc + rB;
            int ic = kr / 9;
            int t9 = kr - ic * 9;
            int kh = t9 / 3;
            int kw = t9 - kh * 3;
            int hh = h + kh - 1;
            bool vh = ((unsigned)hh < 64u);
            const float* rowp = xb + ((size_t)ic * 64 + hh) * 64 + (kw - 1);
#pragma unroll
            for (int i = 0; i < 8; ++i) {
                int w_ = wg + i * 8;
                float v = 0.f;
                if (vh && (unsigned)(w_ + kw - 1) < 64u) v = rowp[w_];
                sB[rB][w_] = v;
            }
        }
        __syncthreads();
#pragma unroll 8
        for (int cc = 0; cc < 32; ++cc) {
            float4 a4 = *(const float4*)&sA[cc][to * 4];
            float4 b4 = *(const float4*)&sB[cc][tp * 4];
            float av[4] = {a4.x, a4.y, a4.z, a4.w};
            float bv[4] = {b4.x, b4.y, b4.z, b4.w};
#pragma unroll
            for (int i = 0; i < 4; ++i)
#pragma unroll
                for (int j = 0; j < 4; ++j)
                    acc[i][j] = fmaf(av[i], bv[j], acc[i][j]);
        }
        __syncthreads();
    }
#pragma unroll
    for (int i = 0; i < 4; ++i) {
        int oc = oc0 + to * 4 + i;
        float bs = bias[oc];
        float4 o = make_float4(acc[i][0] + bs, acc[i][1] + bs,
                               acc[i][2] + bs, acc[i][3] + bs);
        *(float4*)(g_Qraw + ((size_t)(b * CH + oc)) * NQ + h * 64 + tp * 4) = o;
    }
}

// =================================================================
// conv1x1 K+V fused + bias-only border (unchanged from R2)
// =================================================================
__global__ __launch_bounds__(256)
void conv1x1_kernel(const float* __restrict__ x,
                    const float* __restrict__ Wk, const float* __restrict__ Wv,
                    const float* __restrict__ bk, const float* __restrict__ bv)
{
    __shared__ float sAk[32][68], sAv[32][68], sX[32][68];
    const int tid = threadIdx.x;
    const int oc0 = blockIdx.x * 64;
    const int h   = blockIdx.y;
    const int b   = blockIdx.z;
    const int to = tid & 15;
    const int tp = tid >> 4;
    const int ocl = tid >> 2;
    const int rb  = (tid & 3) * 8;
    const int rX  = tid >> 3;
    const int wgx = (tid & 7) * 8;

    float ak[4][4], av2[4][4];
#pragma unroll
    for (int i = 0; i < 4; ++i)
#pragma unroll
        for (int j = 0; j < 4; ++j) { ak[i][j] = 0.f; av2[i][j] = 0.f; }

    for (int kc = 0; kc < 256; kc += 32) {
        const float* wks = Wk + (size_t)(oc0 + ocl) * 256 + kc + rb;
        const float* wvs = Wv + (size_t)(oc0 + ocl) * 256 + kc + rb;
        float4 a0 = *(const float4*)wks;
        float4 a1 = *(const float4*)(wks + 4);
        sAk[rb+0][ocl] = a0.x; sAk[rb+1][ocl] = a0.y; sAk[rb+2][ocl] = a0.z; sAk[rb+3][ocl] = a0.w;
        sAk[rb+4][ocl] = a1.x; sAk[rb+5][ocl] = a1.y; sAk[rb+6][ocl] = a1.z; sAk[rb+7][ocl] = a1.w;
        float4 c0 = *(const float4*)wvs;
        float4 c1 = *(const float4*)(wvs + 4);
        sAv[rb+0][ocl] = c0.x; sAv[rb+1][ocl] = c0.y; sAv[rb+2][ocl] = c0.z; sAv[rb+3][ocl] = c0.w;
        sAv[rb+4][ocl] = c1.x; sAv[rb+5][ocl] = c1.y; sAv[rb+6][ocl] = c1.z; sAv[rb+7][ocl] = c1.w;

        const float* xs = x + ((size_t)(b * CH + kc + rX) * 64 + h) * 64 + wgx;
        float4 x0 = *(const float4*)xs;
        float4 x1 = *(const float4*)(xs + 4);
        *(float4*)&sX[rX][wgx]     = x0;
        *(float4*)&sX[rX][wgx + 4] = x1;
        __syncthreads();
#pragma unroll 8
        for (int cc = 0; cc < 32; ++cc) {
            float4 ka = *(const float4*)&sAk[cc][to * 4];
            float4 va = *(const float4*)&sAv[cc][to * 4];
            float4 xq = *(const float4*)&sX[cc][tp * 4];
            float kr[4] = {ka.x, ka.y, ka.z, ka.w};
            float vr[4] = {va.x, va.y, va.z, va.w};
            float xr[4] = {xq.x, xq.y, xq.z, xq.w};
#pragma unroll
            for (int i = 0; i < 4; ++i)
#pragma unroll
                for (int j = 0; j < 4; ++j) {
                    ak[i][j]  = fmaf(kr[i], xr[j], ak[i][j]);
                    av2[i][j] = fmaf(vr[i], xr[j], av2[i][j]);
                }
        }
        __syncthreads();
    }

    size_t tokbase = (size_t)(h + 1) * 66 + 1 + tp * 4;
#pragma unroll
    for (int i = 0; i < 4; ++i) {
        int oc = oc0 + to * 4 + i;
        float bks = bk[oc], bvs = bv[oc];
        size_t base = ((size_t)(b * CH + oc)) * NK + tokbase;
#pragma unroll
        for (int j = 0; j < 4; ++j) {
            g_Kraw[base + j] = ak[i][j] + bks;
            g_Vraw[base + j] = av2[i][j] + bvs;
        }
    }

    if (h == 0) {
        for (int e = tid; e < 64 * 260; e += 256) {
            int oc = oc0 + (e / 260);
            int p  = e % 260;
            int i2, j2;
            if (p < 66)       { i2 = 0;       j2 = p;       }
            else if (p < 132) { i2 = 65;      j2 = p - 66;  }
            else if (p < 196) { i2 = p - 131; j2 = 0;       }
            else              { i2 = p - 195; j2 = 65;      }
            size_t off = ((size_t)(b * CH + oc)) * NK + i2 * 66 + j2;
            g_Kraw[off] = bk[oc];
            g_Vraw[off] = bv[oc];
        }
    }
}

// =================================================================
// BN statistics -> per-channel affine (unchanged from R2)
// =================================================================
__global__ __launch_bounds__(256)
void bn_stats_kernel(const float* __restrict__ gq, const float* __restrict__ betaq,
                     const float* __restrict__ gk, const float* __restrict__ betak,
                     const float* __restrict__ gv, const float* __restrict__ betav)
{
    const int which = blockIdx.y;
    const float* data  = (which == 0) ? g_Qraw : (which == 1 ? g_Kraw : g_Vraw);
    const float* gamma = (which == 0) ? gq : (which == 1 ? gk : gv);
    const float* beta  = (which == 0) ? betaq : (which == 1 ? betak : betav);
    const int T = (which == 0) ? NQ : NK;
    const int c = blockIdx.x;
    const int tid = threadIdx.x;
    __shared__ float rs[256], rq[256];
    float s = 0.f, s2 = 0.f;
    const int T4 = T & ~3;
    for (int b = 0; b < BATCH; ++b) {
        const float* p = data + ((size_t)(b * CH + c)) * T;
        for (int i = tid * 4; i < T4; i += 1024) {
            float4 v = *(const float4*)(p + i);
            s += v.x + v.y + v.z + v.w;
            s2 = fmaf(v.x, v.x, s2); s2 = fmaf(v.y, v.y, s2);
            s2 = fmaf(v.z, v.z, s2); s2 = fmaf(v.w, v.w, s2);
        }
        for (int i = T4 + tid; i < T; i += 256) {
            float v = p[i];
            s += v;
            s2 = fmaf(v, v, s2);
        }
    }
    rs[tid] = s; rq[tid] = s2;
    __syncthreads();
    for (int off = 128; off > 0; off >>= 1) {
        if (tid < off) { rs[tid] += rs[tid + off]; rq[tid] += rq[tid + off]; }
        __syncthreads();
    }
    if (tid == 0) {
        float n = (float)(BATCH * T);
        float mean = rs[0] / n;
        float var = rq[0] / n - mean * mean;
        if (var < 0.f) var = 0.f;
        float a = gamma[c] * rsqrtf(var + BN_EPS);
        g_aff[(2 * which)     * CH + c] = a;
        g_aff[(2 * which + 1) * CH + c] = beta[c] - mean * a;
    }
}

// =================================================================
// Convert kernels
// =================================================================
// Q: [b][c][q] fp32 -> [b][q][c] bf16 hi/lo (tiled transpose, both sides coalesced)
__global__ __launch_bounds__(256)
void convert_q_kernel()
{
    __shared__ float tile[32][33];
    const int q0 = blockIdx.x * 32, c0 = blockIdx.y * 32, b = blockIdx.z;
    const int tx = threadIdx.x & 31, ty = threadIdx.x >> 5;
    for (int i = ty; i < 32; i += 8)
        tile[i][tx] = g_Qraw[((size_t)(b * CH + c0 + i)) * NQ + q0 + tx];
    __syncthreads();
    const int c = c0 + tx;
    const float a = g_aff[c], s = g_aff[CH + c];
    for (int i = ty; i < 32; i += 8) {
        float v = fmaf(a, tile[tx][i], s);
        __nv_bfloat16 h  = __float2bfloat16_rn(v);
        __nv_bfloat16 lo = __float2bfloat16_rn(v - __bfloat162float(h));
        size_t o = ((size_t)(b * NQ) + q0 + i) * CH + c;
        g_Qh[o] = h; g_Ql[o] = lo;
    }
}

// K: [b][c][tok] fp32 -> [b][tok][c] bf16 hi/lo, zero pad tok >= NK
__global__ __launch_bounds__(256)
void convert_k_kernel()
{
    __shared__ float tile[32][33];
    const int t0 = blockIdx.x * 32, c0 = blockIdx.y * 32, b = blockIdx.z;
    const int tx = threadIdx.x & 31, ty = threadIdx.x >> 5;
    for (int i = ty; i < 32; i += 8) {
        int tok = t0 + tx;
        tile[i][tx] = (tok < NK) ? g_Kraw[((size_t)(b * CH + c0 + i)) * NK + tok] : 0.f;
    }
    __syncthreads();
    const int c = c0 + tx;
    const float a = g_aff[2 * CH + c], s = g_aff[3 * CH + c];
    for (int i = ty; i < 32; i += 8) {
        int tok = t0 + i;
        float v = (tok < NK) ? fmaf(a, tile[tx][i], s) : 0.f;
        __nv_bfloat16 h  = __float2bfloat16_rn(v);
        __nv_bfloat16 lo = __float2bfloat16_rn(v - __bfloat162float(h));
        size_t o = ((size_t)(b * NKP) + tok) * CH + c;
        g_Kh[o] = h; g_Kl[o] = lo;
    }
}

// V: [b][c][tok] fp32 -> [b][t][c][k] fp16 hi/lo
__global__ __launch_bounds__(256)
void convert_v_kernel()
{
    const int t = blockIdx.x, b = blockIdx.y, c = threadIdx.x;
    const float a = g_aff[4 * CH + c], s = g_aff[5 * CH + c];
    const int base = t * 64;
    const float* src = g_Vraw + ((size_t)(b * CH + c)) * NK + base;
    size_t dst = ((size_t)(b * NKT + t) * 256 + c) * 64;
#pragma unroll 8
    for (int k = 0; k < 64; ++k) {
        float v = (base + k < NK) ? fmaf(a, src[k], s) : 0.f;
        __half h  = __float2half_rn(v);
        __half lo = __float2half_rn(v - __half2float(h));
        g_Vh[dst + k] = h; g_Vl[dst + k] = lo;
    }
}

// =================================================================
// mma.sync flash attention.
// CTA = (64-query tile, batch), 8 warps.
// GEMM1: S[64k][64q] = K~Q, bf16 hi/lo x3 mma, fragments kept in regs.
// Softmax from fragments (shfl + small smem partials), P -> fp16 smem.
// GEMM2: O[256c][64q] += V~P, fp16, V hi/lo x2 mma, acc in regs.
// =================================================================
__device__ __forceinline__ uint32_t smem_u32(const void* p) {
    uint32_t a;
    asm("{ .reg .u64 t; cvta.to.shared.u64 t, %1; cvt.u32.u64 %0, t; }" : "=r"(a) : "l"(p));
    return a;
}
__device__ __forceinline__ void ldsm_x4(uint32_t* r, uint32_t addr) {
    asm volatile("ldmatrix.sync.aligned.m8n8.x4.shared.b16 {%0,%1,%2,%3}, [%4];"
        : "=r"(r[0]), "=r"(r[1]), "=r"(r[2]), "=r"(r[3]) : "r"(addr));
}
__device__ __forceinline__ void ldsm_x2(uint32_t* r, uint32_t addr) {
    asm volatile("ldmatrix.sync.aligned.m8n8.x2.shared.b16 {%0,%1}, [%2];"
        : "=r"(r[0]), "=r"(r[1]) : "r"(addr));
}
__device__ __forceinline__ void mma_bf16(float* c, const uint32_t* a, const uint32_t* b) {
    asm volatile("mma.sync.aligned.m16n8k16.row.col.f32.bf16.bf16.f32 "
        "{%0,%1,%2,%3}, {%4,%5,%6,%7}, {%8,%9}, {%0,%1,%2,%3};"
        : "+f"(c[0]), "+f"(c[1]), "+f"(c[2]), "+f"(c[3])
        : "r"(a[0]), "r"(a[1]), "r"(a[2]), "r"(a[3]), "r"(b[0]), "r"(b[1]));
}
__device__ __forceinline__ void mma_f16(float* c, const uint32_t* a, const uint32_t* b) {
    asm volatile("mma.sync.aligned.m16n8k16.row.col.f32.f16.f16.f32 "
        "{%0,%1,%2,%3}, {%4,%5,%6,%7}, {%8,%9}, {%0,%1,%2,%3};"
        : "+f"(c[0]), "+f"(c[1]), "+f"(c[2]), "+f"(c[3])
        : "r"(a[0]), "r"(a[1]), "r"(a[2]), "r"(a[3]), "r"(b[0]), "r"(b[1]));
}

struct __align__(16) FS {
    __nv_bfloat16 Qh[64 * 264];   // [q][c] pad 264 (528B rows, 16B aligned, conflict-free)
    __nv_bfloat16 Ql[64 * 264];
    __nv_bfloat16 Kh[64 * 264];   // [k][c]
    __nv_bfloat16 Kl[64 * 264];
    __half Vh[256 * 72];          // [c][k] pad 72 (144B rows)
    __half Vl[256 * 72];
    __half P[64 * 72];            // [q][k] pad 72
    float m[64], l[64], r[64];
    float pm[4][64], ps[4][64];
};

__global__ __launch_bounds__(256, 1)
void flash_mma_kernel(float* __restrict__ out)
{
    extern __shared__ char smem_raw[];
    FS* S = (FS*)smem_raw;
    const int tid = threadIdx.x;
    const int wid = tid >> 5, lane = tid & 31;
    const int b = blockIdx.y, qt = blockIdx.x, q0 = qt * 64;

    if (tid < 64) { S->m[tid] = -1e30f; S->l[tid] = 0.f; }

    // ---- load Q tile (64 x 256 hi/lo) ----
    {
        int row = tid >> 2, seg = tid & 3;
        const uint4* sh = (const uint4*)(g_Qh + ((size_t)(b * NQ + q0 + row)) * CH);
        const uint4* sl = (const uint4*)(g_Ql + ((size_t)(b * NQ + q0 + row)) * CH);
        uint4* dh = (uint4*)&S->Qh[row * 264];
        uint4* dl = (uint4*)&S->Ql[row * 264];
#pragma unroll
        for (int i = 0; i < 8; ++i) { dh[seg*8+i] = sh[seg*8+i]; dl[seg*8+i] = sl[seg*8+i]; }
    }

    const int strip = wid & 3;    // GEMM1 k-row strip (16 rows)
    const int ng    = wid >> 2;   // GEMM1 q-col group (32 cols)
    // GEMM1 ldmatrix lane addressing
    const int a_r = strip * 16 + (lane & 15);
    const int a_c = ((lane >> 4) & 1) * 8;
    const uint32_t aKh = smem_u32(&S->Kh[a_r * 264 + a_c]);
    const uint32_t aKl = smem_u32(&S->Kl[a_r * 264 + a_c]);
    const int b_r = ng * 32 + (lane & 7);
    const int b_c = ((lane >> 3) & 1) * 8;
    const uint32_t bQh = smem_u32(&S->Qh[b_r * 264 + b_c]);
    const uint32_t bQl = smem_u32(&S->Ql[b_r * 264 + b_c]);
    // GEMM2 ldmatrix lane addressing
    const uint32_t aVh = smem_u32(&S->Vh[(wid * 32 + (lane & 15)) * 72 + ((lane >> 4) & 1) * 8]);
    const uint32_t aVl = smem_u32(&S->Vl[(wid * 32 + (lane & 15)) * 72 + ((lane >> 4) & 1) * 8]);
    const uint32_t bP  = smem_u32(&S->P[(lane & 7) * 72 + ((lane >> 3) & 1) * 8]);

    const int r0 = strip * 16 + (lane >> 2);   // fragment row (k) for this thread
    const int r1 = r0 + 8;
    const int cpair = (lane & 3) * 2;          // fragment col offset within n-tile

    float acc[16][4];                          // GEMM2: [strip2*8+nt][4]
#pragma unroll
    for (int i = 0; i < 16; ++i)
#pragma unroll
        for (int j = 0; j < 4; ++j) acc[i][j] = 0.f;

    __syncthreads();

    for (int t = 0; t < NKT; ++t) {
        // ---- load K tile hi/lo ----
        {
            int row = tid >> 2, seg = tid & 3;
            const uint4* sh = (const uint4*)(g_Kh + ((size_t)(b * NKP + t * 64 + row)) * CH);
            const uint4* sl = (const uint4*)(g_Kl + ((size_t)(b * NKP + t * 64 + row)) * CH);
            uint4* dh = (uint4*)&S->Kh[row * 264];
            uint4* dl = (uint4*)&S->Kl[row * 264];
#pragma unroll
            for (int i = 0; i < 8; ++i) { dh[seg*8+i] = sh[seg*8+i]; dl[seg*8+i] = sl[seg*8+i]; }
        }
        // ---- load V tile hi/lo ----
        {
            const uint4* sh = (const uint4*)(g_Vh + ((size_t)(b * NKT + t) * 256 + tid) * 64);
            const uint4* sl = (const uint4*)(g_Vl + ((size_t)(b * NKT + t) * 256 + tid) * 64);
            uint4* dh = (uint4*)&S->Vh[tid * 72];
            uint4* dl = (uint4*)&S->Vl[tid * 72];
#pragma unroll
            for (int i = 0; i < 8; ++i) { dh[i] = sh[i]; dl[i] = sl[i]; }
        }
        __syncthreads();

        // ---- GEMM1: score fragments ----
        float sc[4][4];
#pragma unroll
        for (int i = 0; i < 4; ++i)
#pragma unroll
            for (int j = 0; j < 4; ++j) sc[i][j] = 0.f;
#pragma unroll
        for (int kc = 0; kc < 256; kc += 16) {
            uint32_t ah[4], al[4];
            ldsm_x4(ah, aKh + kc * 2);
            ldsm_x4(al, aKl + kc * 2);
#pragma unroll
            for (int nt = 0; nt < 4; ++nt) {
                uint32_t bh[2], bl[2];
                ldsm_x2(bh, bQh + nt * 4224 + kc * 2);   // nt*8 rows * 264 * 2B
                ldsm_x2(bl, bQl + nt * 4224 + kc * 2);
                mma_bf16(sc[nt], ah, bh);
                mma_bf16(sc[nt], ah, bl);
                mma_bf16(sc[nt], al, bh);
            }
        }

        // ---- softmax from fragments ----
        const int kvalid = NK - t * 64 < 64 ? NK - t * 64 : 64;
        const bool v0 = r0 < kvalid, v1 = r1 < kvalid;
        {
            float px[4][2];
#pragma unroll
            for (int nt = 0; nt < 4; ++nt) {
                px[nt][0] = fmaxf(v0 ? sc[nt][0] : -1e30f, v1 ? sc[nt][2] : -1e30f);
                px[nt][1] = fmaxf(v0 ? sc[nt][1] : -1e30f, v1 ? sc[nt][3] : -1e30f);
            }
#pragma unroll
            for (int off = 4; off < 32; off <<= 1)
#pragma unroll
                for (int nt = 0; nt < 4; ++nt) {
                    px[nt][0] = fmaxf(px[nt][0], __shfl_xor_sync(~0u, px[nt][0], off));
                    px[nt][1] = fmaxf(px[nt][1], __shfl_xor_sync(~0u, px[nt][1], off));
                }
            if (lane < 4) {
#pragma unroll
                for (int nt = 0; nt < 4; ++nt) {
                    int col = ng * 32 + nt * 8 + lane * 2;
                    S->pm[strip][col]     = px[nt][0];
                    S->pm[strip][col + 1] = px[nt][1];
                }
            }
        }
        __syncthreads();
        if (tid < 64) {
            float mold = S->m[tid];
            float mx = fmaxf(fmaxf(S->pm[0][tid], S->pm[1][tid]),
                             fmaxf(S->pm[2][tid], S->pm[3][tid]));
            float mnew = fmaxf(mold, mx);
            S->m[tid] = mnew;
            S->r[tid] = __expf(mold - mnew);
        }
        __syncthreads();
        {
            float pssum[4][2];
#pragma unroll
            for (int nt = 0; nt < 4; ++nt) {
                int col = ng * 32 + nt * 8 + cpair;
                float m0 = S->m[col], m1 = S->m[col + 1];
                float e00 = v0 ? __expf(sc[nt][0] - m0) : 0.f;
                float e01 = v0 ? __expf(sc[nt][1] - m1) : 0.f;
                float e10 = v1 ? __expf(sc[nt][2] - m0) : 0.f;
                float e11 = v1 ? __expf(sc[nt][3] - m1) : 0.f;
                S->P[col * 72 + r0]       = __float2half_rn(e00);
                S->P[(col + 1) * 72 + r0] = __float2half_rn(e01);
                S->P[col * 72 + r1]       = __float2half_rn(e10);
                S->P[(col + 1) * 72 + r1] = __float2half_rn(e11);
                pssum[nt][0] = e00 + e10;
                pssum[nt][1] = e01 + e11;
            }
#pragma unroll
            for (int off = 4; off < 32; off <<= 1)
#pragma unroll
                for (int nt = 0; nt < 4; ++nt) {
                    pssum[nt][0] += __shfl_xor_sync(~0u, pssum[nt][0], off);
                    pssum[nt][1] += __shfl_xor_sync(~0u, pssum[nt][1], off);
                }
            if (lane < 4) {
#pragma unroll
                for (int nt = 0; nt < 4; ++nt) {
                    int col = ng * 32 + nt * 8 + lane * 2;
                    S->ps[strip][col]     = pssum[nt][0];
                    S->ps[strip][col + 1] = pssum[nt][1];
                }
            }
        }
        __syncthreads();
        if (tid < 64) {
            S->l[tid] = S->l[tid] * S->r[tid]
                      + ((S->ps[0][tid] + S->ps[1][tid]) + (S->ps[2][tid] + S->ps[3][tid]));
        }

        // ---- GEMM2: rescale + accumulate ----
#pragma unroll
        for (int i = 0; i < 16; ++i) {
            int col = (i & 7) * 8 + cpair;
            float rv0 = S->r[col], rv1 = S->r[col + 1];
            acc[i][0] *= rv0; acc[i][1] *= rv1;
            acc[i][2] *= rv0; acc[i][3] *= rv1;
        }
#pragma unroll
        for (int kc = 0; kc < 64; kc += 16) {
            uint32_t pb[8][2];
#pragma unroll
            for (int nt = 0; nt < 8; ++nt)
                ldsm_x2(pb[nt], bP + nt * 1152 + kc * 2);   // nt*8 rows * 72 * 2B
#pragma unroll
            for (int s2 = 0; s2 < 2; ++s2) {
                uint32_t vh[4], vl[4];
                ldsm_x4(vh, aVh + s2 * 2304 + kc * 2);      // s2*16 rows * 72 * 2B
                ldsm_x4(vl, aVl + s2 * 2304 + kc * 2);
#pragma unroll
                for (int nt = 0; nt < 8; ++nt) {
                    mma_f16(acc[s2 * 8 + nt], vh, pb[nt]);
                    mma_f16(acc[s2 * 8 + nt], vl, pb[nt]);
                }
            }
        }
        __syncthreads();
    }

    // ---- epilogue ----
#pragma unroll
    for (int i = 0; i < 16; ++i) {
        int s2 = i >> 3, nt = i & 7;
        int col = nt * 8 + cpair;
        float li0 = 1.f / S->l[col], li1 = 1.f / S->l[col + 1];
        int row = wid * 32 + s2 * 16 + (lane >> 2);
        size_t o0 = ((size_t)(b * CH + row)) * NQ + q0 + col;
        size_t o1 = ((size_t)(b * CH + row + 8)) * NQ + q0 + col;
        out[o0]     = acc[i][0] * li0;
        out[o0 + 1] = acc[i][1] * li1;
        out[o1]     = acc[i][2] * li0;
        out[o1 + 1] = acc[i][3] * li1;
    }
}

// =================================================================
extern "C" void kernel_launch(void* const* d_in, const int* in_sizes, int n_in,
                              void* d_out, int out_size)
{
    (void)in_sizes; (void)n_in; (void)out_size;
    const float* x     = (const float*)d_in[0];
    const float* Wq    = (const float*)d_in[1];
    const float* bq    = (const float*)d_in[2];
    const float* gq    = (const float*)d_in[3];
    const float* betaq = (const float*)d_in[4];
    const float* Wk    = (const float*)d_in[5];
    const float* bk    = (const float*)d_in[6];
    const float* gk    = (const float*)d_in[7];
    const float* betak = (const float*)d_in[8];
    const float* Wv    = (const float*)d_in[9];
    const float* bv    = (const float*)d_in[10];
    const float* gv    = (const float*)d_in[11];
    const float* betav = (const float*)d_in[12];
    float* out = (float*)d_out;

    conv3x3_kernel<<<dim3(4, 64, BATCH), 256>>>(x, Wq, bq);
    conv1x1_kernel<<<dim3(4, 64, BATCH), 256>>>(x, Wk, Wv, bk, bv);
    bn_stats_kernel<<<dim3(CH, 3), 256>>>(gq, betaq, gk, betak, gv, betav);
    convert_q_kernel<<<dim3(NQ / 32, CH / 32, BATCH), 256>>>();
    convert_k_kernel<<<dim3(NKP / 32, CH / 32, BATCH), 256>>>();
    convert_v_kernel<<<dim3(NKT, BATCH), 256>>>();

    cudaFuncSetAttribute(flash_mma_kernel,
                         cudaFuncAttributeMaxDynamicSharedMemorySize,
                         (int)sizeof(FS));
    flash_mma_kernel<<<dim3(NQ / 64, BATCH), 256, sizeof(FS)>>>(out);
}

// round 9
// speedup vs baseline: 2.4369x; 1.3035x over previous
#include <cuda_runtime.h>
#include <cuda_bf16.h>
#include <cuda_fp16.h>
#include <cstdint>

#define BATCH 4
#define CH 256
#define NQ 4096        /* 64*64 query tokens per batch  */
#define NK 4356        /* 66*66 key tokens per batch    */
#define NKT 69         /* key tiles of 64 (padded 4416) */
#define NKP (NKT * 64)
#define BN_EPS 1e-5f

// ---------------- scratch (no allocations allowed) ----------------
__device__ float g_Qraw[BATCH * CH * NQ];
__device__ float g_Kraw[BATCH * CH * NK];
__device__ float g_Vraw[BATCH * CH * NK];
__device__ float g_aff[6 * CH];             // aQ,bQ,aK,bK,aV,bV
// converted operands
__device__ __nv_bfloat16 g_Qh[BATCH * NQ * CH];      // [b][q][c]
__device__ __nv_bfloat16 g_Ql[BATCH * NQ * CH];
__device__ __nv_bfloat16 g_Kh[BATCH * NKP * CH];     // [b][tok][c] (zero-padded tail)
__device__ __nv_bfloat16 g_Kl[BATCH * NKP * CH];
__device__ __half        g_Vh[BATCH * NKT * 256 * 64]; // [b][t][c][k]
__device__ __half        g_Vl[BATCH * NKT * 256 * 64];

// =================================================================
// Fused conv kernel: blockIdx.x < 4 -> conv3x3 (Q); >= 4 -> conv1x1 (K,V)
// =================================================================
__global__ __launch_bounds__(256)
void fused_conv_kernel(const float* __restrict__ x,
                       const float* __restrict__ Wq, const float* __restrict__ bq,
                       const float* __restrict__ Wk, const float* __restrict__ Wv,
                       const float* __restrict__ bk, const float* __restrict__ bv)
{
    __shared__ float sm[3][32][68];
    const int tid = threadIdx.x;
    const int h   = blockIdx.y;
    const int b   = blockIdx.z;
    const int to = tid & 15;
    const int tp = tid >> 4;
    const int ocl = tid >> 2;
    const int rb  = (tid & 3) * 8;

    if (blockIdx.x < 4) {
        // ---------------- conv3x3 ----------------
        const int oc0 = blockIdx.x * 64;
        const int rB  = tid >> 3;
        const int wg  = tid & 7;
        const float* xb = x + (size_t)b * CH * NQ;
        float acc[4][4];
#pragma unroll
        for (int i = 0; i < 4; ++i)
#pragma unroll
            for (int j = 0; j < 4; ++j) acc[i][j] = 0.f;

        for (int kc = 0; kc < 2304; kc += 32) {
            const float* wsrc = Wq + (size_t)(oc0 + ocl) * 2304 + kc + rb;
            float4 w0 = *(const float4*)wsrc;
            float4 w1 = *(const float4*)(wsrc + 4);
            sm[0][rb+0][ocl] = w0.x; sm[0][rb+1][ocl] = w0.y; sm[0][rb+2][ocl] = w0.z; sm[0][rb+3][ocl] = w0.w;
            sm[0][rb+4][ocl] = w1.x; sm[0][rb+5][ocl] = w1.y; sm[0][rb+6][ocl] = w1.z; sm[0][rb+7][ocl] = w1.w;
            {
                int kr = kc + rB;
                int ic = kr / 9;
                int t9 = kr - ic * 9;
                int kh = t9 / 3;
                int kw = t9 - kh * 3;
                int hh = h + kh - 1;
                bool vh = ((unsigned)hh < 64u);
                const float* rowp = xb + ((size_t)ic * 64 + hh) * 64 + (kw - 1);
#pragma unroll
                for (int i = 0; i < 8; ++i) {
                    int w_ = wg + i * 8;
                    float v = 0.f;
                    if (vh && (unsigned)(w_ + kw - 1) < 64u) v = rowp[w_];
                    sm[1][rB][w_] = v;
                }
            }
            __syncthreads();
#pragma unroll 8
            for (int cc = 0; cc < 32; ++cc) {
                float4 a4 = *(const float4*)&sm[0][cc][to * 4];
                float4 b4 = *(const float4*)&sm[1][cc][tp * 4];
                float av[4] = {a4.x, a4.y, a4.z, a4.w};
                float bv2[4] = {b4.x, b4.y, b4.z, b4.w};
#pragma unroll
                for (int i = 0; i < 4; ++i)
#pragma unroll
                    for (int j = 0; j < 4; ++j)
                        acc[i][j] = fmaf(av[i], bv2[j], acc[i][j]);
            }
            __syncthreads();
        }
#pragma unroll
        for (int i = 0; i < 4; ++i) {
            int oc = oc0 + to * 4 + i;
            float bs = bq[oc];
            float4 o = make_float4(acc[i][0] + bs, acc[i][1] + bs,
                                   acc[i][2] + bs, acc[i][3] + bs);
            *(float4*)(g_Qraw + ((size_t)(b * CH + oc)) * NQ + h * 64 + tp * 4) = o;
        }
    } else {
        // ---------------- conv1x1 (K, V) ----------------
        const int oc0 = (blockIdx.x - 4) * 64;
        const int rX  = tid >> 3;
        const int wgx = (tid & 7) * 8;
        float ak[4][4], av2[4][4];
#pragma unroll
        for (int i = 0; i < 4; ++i)
#pragma unroll
            for (int j = 0; j < 4; ++j) { ak[i][j] = 0.f; av2[i][j] = 0.f; }

        for (int kc = 0; kc < 256; kc += 32) {
            const float* wks = Wk + (size_t)(oc0 + ocl) * 256 + kc + rb;
            const float* wvs = Wv + (size_t)(oc0 + ocl) * 256 + kc + rb;
            float4 a0 = *(const float4*)wks;
            float4 a1 = *(const float4*)(wks + 4);
            sm[0][rb+0][ocl] = a0.x; sm[0][rb+1][ocl] = a0.y; sm[0][rb+2][ocl] = a0.z; sm[0][rb+3][ocl] = a0.w;
            sm[0][rb+4][ocl] = a1.x; sm[0][rb+5][ocl] = a1.y; sm[0][rb+6][ocl] = a1.z; sm[0][rb+7][ocl] = a1.w;
            float4 c0 = *(const float4*)wvs;
            float4 c1 = *(const float4*)(wvs + 4);
            sm[1][rb+0][ocl] = c0.x; sm[1][rb+1][ocl] = c0.y; sm[1][rb+2][ocl] = c0.z; sm[1][rb+3][ocl] = c0.w;
            sm[1][rb+4][ocl] = c1.x; sm[1][rb+5][ocl] = c1.y; sm[1][rb+6][ocl] = c1.z; sm[1][rb+7][ocl] = c1.w;

            const float* xs = x + ((size_t)(b * CH + kc + rX) * 64 + h) * 64 + wgx;
            float4 x0 = *(const float4*)xs;
            float4 x1 = *(const float4*)(xs + 4);
            *(float4*)&sm[2][rX][wgx]     = x0;
            *(float4*)&sm[2][rX][wgx + 4] = x1;
            __syncthreads();
#pragma unroll 8
            for (int cc = 0; cc < 32; ++cc) {
                float4 ka = *(const float4*)&sm[0][cc][to * 4];
                float4 va = *(const float4*)&sm[1][cc][to * 4];
                float4 xq = *(const float4*)&sm[2][cc][tp * 4];
                float kr[4] = {ka.x, ka.y, ka.z, ka.w};
                float vr[4] = {va.x, va.y, va.z, va.w};
                float xr[4] = {xq.x, xq.y, xq.z, xq.w};
#pragma unroll
                for (int i = 0; i < 4; ++i)
#pragma unroll
                    for (int j = 0; j < 4; ++j) {
                        ak[i][j]  = fmaf(kr[i], xr[j], ak[i][j]);
                        av2[i][j] = fmaf(vr[i], xr[j], av2[i][j]);
                    }
            }
            __syncthreads();
        }

        size_t tokbase = (size_t)(h + 1) * 66 + 1 + tp * 4;
#pragma unroll
        for (int i = 0; i < 4; ++i) {
            int oc = oc0 + to * 4 + i;
            float bks = bk[oc], bvs = bv[oc];
            size_t base = ((size_t)(b * CH + oc)) * NK + tokbase;
#pragma unroll
            for (int j = 0; j < 4; ++j) {
                g_Kraw[base + j] = ak[i][j] + bks;
                g_Vraw[base + j] = av2[i][j] + bvs;
            }
        }

        if (h == 0) {
            for (int e = tid; e < 64 * 260; e += 256) {
                int oc = oc0 + (e / 260);
                int p  = e % 260;
                int i2, j2;
                if (p < 66)       { i2 = 0;       j2 = p;       }
                else if (p < 132) { i2 = 65;      j2 = p - 66;  }
                else if (p < 196) { i2 = p - 131; j2 = 0;       }
                else              { i2 = p - 195; j2 = 65;      }
                size_t off = ((size_t)(b * CH + oc)) * NK + i2 * 66 + j2;
                g_Kraw[off] = bk[oc];
                g_Vraw[off] = bv[oc];
            }
        }
    }
}

// =================================================================
// BN statistics -> per-channel affine (unchanged)
// =================================================================
__global__ __launch_bounds__(256)
void bn_stats_kernel(const float* __restrict__ gq, const float* __restrict__ betaq,
                     const float* __restrict__ gk, const float* __restrict__ betak,
                     const float* __restrict__ gv, const float* __restrict__ betav)
{
    const int which = blockIdx.y;
    const float* data  = (which == 0) ? g_Qraw : (which == 1 ? g_Kraw : g_Vraw);
    const float* gamma = (which == 0) ? gq : (which == 1 ? gk : gv);
    const float* beta  = (which == 0) ? betaq : (which == 1 ? betak : betav);
    const int T = (which == 0) ? NQ : NK;
    const int c = blockIdx.x;
    const int tid = threadIdx.x;
    __shared__ float rs[256], rq[256];
    float s = 0.f, s2 = 0.f;
    const int T4 = T & ~3;
    for (int b = 0; b < BATCH; ++b) {
        const float* p = data + ((size_t)(b * CH + c)) * T;
        for (int i = tid * 4; i < T4; i += 1024) {
            float4 v = *(const float4*)(p + i);
            s += v.x + v.y + v.z + v.w;
            s2 = fmaf(v.x, v.x, s2); s2 = fmaf(v.y, v.y, s2);
            s2 = fmaf(v.z, v.z, s2); s2 = fmaf(v.w, v.w, s2);
        }
        for (int i = T4 + tid; i < T; i += 256) {
            float v = p[i];
            s += v;
            s2 = fmaf(v, v, s2);
        }
    }
    rs[tid] = s; rq[tid] = s2;
    __syncthreads();
    for (int off = 128; off > 0; off >>= 1) {
        if (tid < off) { rs[tid] += rs[tid + off]; rq[tid] += rq[tid + off]; }
        __syncthreads();
    }
    if (tid == 0) {
        float n = (float)(BATCH * T);
        float mean = rs[0] / n;
        float var = rq[0] / n - mean * mean;
        if (var < 0.f) var = 0.f;
        float a = gamma[c] * rsqrtf(var + BN_EPS);
        g_aff[(2 * which)     * CH + c] = a;
        g_aff[(2 * which + 1) * CH + c] = beta[c] - mean * a;
    }
}

// =================================================================
// Fused convert kernel: y<8 Q, 8<=y<16 K, y==16 V
// =================================================================
__global__ __launch_bounds__(256)
void fused_convert_kernel()
{
    __shared__ float tile[32][33];
    const int b = blockIdx.z;
    const int tx = threadIdx.x & 31, ty = threadIdx.x >> 5;

    if (blockIdx.y < 8) {
        if (blockIdx.x >= NQ / 32) return;
        const int q0 = blockIdx.x * 32, c0 = blockIdx.y * 32;
        for (int i = ty; i < 32; i += 8)
            tile[i][tx] = g_Qraw[((size_t)(b * CH + c0 + i)) * NQ + q0 + tx];
        __syncthreads();
        const int c = c0 + tx;
        const float a = g_aff[c], s = g_aff[CH + c];
        for (int i = ty; i < 32; i += 8) {
            float v = fmaf(a, tile[tx][i], s);
            __nv_bfloat16 h  = __float2bfloat16_rn(v);
            __nv_bfloat16 lo = __float2bfloat16_rn(v - __bfloat162float(h));
            size_t o = ((size_t)(b * NQ) + q0 + i) * CH + c;
            g_Qh[o] = h; g_Ql[o] = lo;
        }
    } else if (blockIdx.y < 16) {
        const int t0 = blockIdx.x * 32, c0 = (blockIdx.y - 8) * 32;
        for (int i = ty; i < 32; i += 8) {
            int tok = t0 + tx;
            tile[i][tx] = (tok < NK) ? g_Kraw[((size_t)(b * CH + c0 + i)) * NK + tok] : 0.f;
        }
        __syncthreads();
        const int c = c0 + tx;
        const float a = g_aff[2 * CH + c], s = g_aff[3 * CH + c];
        for (int i = ty; i < 32; i += 8) {
            int tok = t0 + i;
            float v = (tok < NK) ? fmaf(a, tile[tx][i], s) : 0.f;
            __nv_bfloat16 h  = __float2bfloat16_rn(v);
            __nv_bfloat16 lo = __float2bfloat16_rn(v - __bfloat162float(h));
            size_t o = ((size_t)(b * NKP) + tok) * CH + c;
            g_Kh[o] = h; g_Kl[o] = lo;
        }
    } else {
        if (blockIdx.x >= NKT) return;
        const int t = blockIdx.x;
        const int kl = threadIdx.x & 63, cg = threadIdx.x >> 6;
        const int base = t * 64;
        const int tok = base + kl;
        const bool valid = tok < NK;
        for (int c = cg; c < CH; c += 4) {
            float v = 0.f;
            if (valid)
                v = fmaf(g_aff[4 * CH + c], g_Vraw[((size_t)(b * CH + c)) * NK + tok], g_aff[5 * CH + c]);
            __half h  = __float2half_rn(v);
            __half lo = __float2half_rn(v - __half2float(h));
            size_t dst = ((size_t)(b * NKT + t) * 256 + c) * 64 + kl;
            g_Vh[dst] = h; g_Vl[dst] = lo;
        }
    }
}

// =================================================================
// mma.sync flash attention, software-pipelined cp.async K/V loads.
// =================================================================
__device__ __forceinline__ uint32_t smem_u32(const void* p) {
    uint32_t a;
    asm("{ .reg .u64 t; cvta.to.shared.u64 t, %1; cvt.u32.u64 %0, t; }" : "=r"(a) : "l"(p));
    return a;
}
__device__ __forceinline__ void ldsm_x4(uint32_t* r, uint32_t addr) {
    asm volatile("ldmatrix.sync.aligned.m8n8.x4.shared.b16 {%0,%1,%2,%3}, [%4];"
        : "=r"(r[0]), "=r"(r[1]), "=r"(r[2]), "=r"(r[3]) : "r"(addr));
}
__device__ __forceinline__ void mma_bf16(float* c, const uint32_t* a, const uint32_t* b) {
    asm volatile("mma.sync.aligned.m16n8k16.row.col.f32.bf16.bf16.f32 "
        "{%0,%1,%2,%3}, {%4,%5,%6,%7}, {%8,%9}, {%0,%1,%2,%3};"
        : "+f"(c[0]), "+f"(c[1]), "+f"(c[2]), "+f"(c[3])
        : "r"(a[0]), "r"(a[1]), "r"(a[2]), "r"(a[3]), "r"(b[0]), "r"(b[1]));
}
__device__ __forceinline__ void mma_f16(float* c, const uint32_t* a, const uint32_t* b) {
    asm volatile("mma.sync.aligned.m16n8k16.row.col.f32.f16.f16.f32 "
        "{%0,%1,%2,%3}, {%4,%5,%6,%7}, {%8,%9}, {%0,%1,%2,%3};"
        : "+f"(c[0]), "+f"(c[1]), "+f"(c[2]), "+f"(c[3])
        : "r"(a[0]), "r"(a[1]), "r"(a[2]), "r"(a[3]), "r"(b[0]), "r"(b[1]));
}
__device__ __forceinline__ void cp16(uint32_t s, const void* g) {
    asm volatile("cp.async.cg.shared.global [%0], [%1], 16;" :: "r"(s), "l"(g));
}
#define CP_COMMIT()  asm volatile("cp.async.commit_group;" ::: "memory")
#define CP_WAIT0()   asm volatile("cp.async.wait_group 0;" ::: "memory")
#define CP_WAIT1()   asm volatile("cp.async.wait_group 1;" ::: "memory")

struct __align__(16) FS {
    __nv_bfloat16 Qh[64 * 264];   // [q][c] pad 264 (528B rows, conflict-free)
    __nv_bfloat16 Ql[64 * 264];
    __nv_bfloat16 Kh[64 * 264];   // [k][c]
    __nv_bfloat16 Kl[64 * 264];
    __half Vh[256 * 72];          // [c][k] pad 72 (144B rows)
    __half Vl[256 * 72];
    __half P[64 * 72];            // [q][k] pad 72
    float m[64], l[64], r[64];
    float pm[4][64], ps[4][64];
};

__global__ __launch_bounds__(256, 1)
void flash_mma_kernel(float* __restrict__ out)
{
    extern __shared__ char smem_raw[];
    FS* S = (FS*)smem_raw;
    const int tid = threadIdx.x;
    const int wid = tid >> 5, lane = tid & 31;
    const int b = blockIdx.y, qt = blockIdx.x, q0 = qt * 64;

    if (tid < 64) { S->m[tid] = -1e30f; S->l[tid] = 0.f; }

    // ---- load Q tile (64 x 256 hi/lo) ----
    {
        int row = tid >> 2, seg = tid & 3;
        const uint4* sh = (const uint4*)(g_Qh + ((size_t)(b * NQ + q0 + row)) * CH);
        const uint4* sl = (const uint4*)(g_Ql + ((size_t)(b * NQ + q0 + row)) * CH);
        uint4* dh = (uint4*)&S->Qh[row * 264];
        uint4* dl = (uint4*)&S->Ql[row * 264];
#pragma unroll
        for (int i = 0; i < 8; ++i) { dh[seg*8+i] = sh[seg*8+i]; dl[seg*8+i] = sl[seg*8+i]; }
    }

    const int strip = wid & 3;    // GEMM1 k-row strip (16 rows)
    const int ng    = wid >> 2;   // GEMM1 q-col group (32 cols)
    // GEMM1 A (K) ldmatrix addressing
    const int a_r = strip * 16 + (lane & 15);
    const int a_c = ((lane >> 4) & 1) * 8;
    const uint32_t aKh = smem_u32(&S->Kh[a_r * 264 + a_c]);
    const uint32_t aKl = smem_u32(&S->Kl[a_r * 264 + a_c]);
    // GEMM1 B (Q) x4 addressing: mats {0,1}=nt even, {2,3}=nt odd
    const int b4_r = ng * 32 + ((lane >> 4) & 1) * 8 + (lane & 7);
    const int b4_c = ((lane >> 3) & 1) * 8;
    const uint32_t bQh4 = smem_u32(&S->Qh[b4_r * 264 + b4_c]);
    const uint32_t bQl4 = smem_u32(&S->Ql[b4_r * 264 + b4_c]);
    // GEMM2 A (V) addressing
    const uint32_t aVh = smem_u32(&S->Vh[(wid * 32 + (lane & 15)) * 72 + ((lane >> 4) & 1) * 8]);
    const uint32_t aVl = smem_u32(&S->Vl[(wid * 32 + (lane & 15)) * 72 + ((lane >> 4) & 1) * 8]);
    // GEMM2 B (P) x4 addressing
    const int p4_r = ((lane >> 4) & 1) * 8 + (lane & 7);
    const uint32_t bP4 = smem_u32(&S->P[p4_r * 72 + ((lane >> 3) & 1) * 8]);

    const int r0 = strip * 16 + (lane >> 2);
    const int r1 = r0 + 8;
    const int cpair = (lane & 3) * 2;

    // cp.async staging addresses
    const int krow = tid >> 2, kseg = tid & 3;
    const uint32_t dKh = smem_u32(&S->Kh[krow * 264]) + kseg * 128;
    const uint32_t dKl = smem_u32(&S->Kl[krow * 264]) + kseg * 128;
    const uint32_t dVh = smem_u32(&S->Vh[tid * 72]);
    const uint32_t dVl = smem_u32(&S->Vl[tid * 72]);

    // prefetch issue helpers (one commit group each)
    auto issue_K = [&](int t) {
        const char* sKh = (const char*)(g_Kh + ((size_t)(b * NKP + t * 64 + krow)) * CH) + kseg * 128;
        const char* sKl = (const char*)(g_Kl + ((size_t)(b * NKP + t * 64 + krow)) * CH) + kseg * 128;
#pragma unroll
        for (int i = 0; i < 8; ++i) {
            cp16(dKh + i * 16, sKh + i * 16);
            cp16(dKl + i * 16, sKl + i * 16);
        }
        CP_COMMIT();
    };
    auto issue_V = [&](int t) {
        const char* sVh = (const char*)(g_Vh + ((size_t)(b * NKT + t) * 256 + tid) * 64);
        const char* sVl = (const char*)(g_Vl + ((size_t)(b * NKT + t) * 256 + tid) * 64);
#pragma unroll
        for (int i = 0; i < 8; ++i) {
            cp16(dVh + i * 16, sVh + i * 16);
            cp16(dVl + i * 16, sVl + i * 16);
        }
        CP_COMMIT();
    };

    float acc[16][4];
#pragma unroll
    for (int i = 0; i < 16; ++i)
#pragma unroll
        for (int j = 0; j < 4; ++j) acc[i][j] = 0.f;

    // preload tile 0: groups committed in order [K0, V0]
    issue_K(0);
    issue_V(0);
    __syncthreads();

    for (int t = 0; t < NKT; ++t) {
        // outstanding groups (commit order): [K_t, V_t]  ->  wait K_t
        CP_WAIT1();
        __syncthreads();

        // ---- GEMM1: score fragments ----
        float sc[4][4];
#pragma unroll
        for (int i = 0; i < 4; ++i)
#pragma unroll
            for (int j = 0; j < 4; ++j) sc[i][j] = 0.f;
#pragma unroll
        for (int kc = 0; kc < 256; kc += 16) {
            uint32_t ah[4], al[4], bh4[2][4], bl4[2][4];
            ldsm_x4(ah, aKh + kc * 2);
            ldsm_x4(al, aKl + kc * 2);
            ldsm_x4(bh4[0], bQh4 + kc * 2);
            ldsm_x4(bh4[1], bQh4 + 16 * 264 * 2 + kc * 2);
            ldsm_x4(bl4[0], bQl4 + kc * 2);
            ldsm_x4(bl4[1], bQl4 + 16 * 264 * 2 + kc * 2);
#pragma unroll
            for (int nt = 0; nt < 4; ++nt) {
                const uint32_t* bh = &bh4[nt >> 1][(nt & 1) * 2];
                const uint32_t* bl = &bl4[nt >> 1][(nt & 1) * 2];
                mma_bf16(sc[nt], ah, bh);
                mma_bf16(sc[nt], ah, bl);
                mma_bf16(sc[nt], al, bh);
            }
        }

        // ---- softmax part 1: per-column partial max ----
        const int kvalid = NK - t * 64 < 64 ? NK - t * 64 : 64;
        const bool v0 = r0 < kvalid, v1 = r1 < kvalid;
        {
            float px[4][2];
#pragma unroll
            for (int nt = 0; nt < 4; ++nt) {
                px[nt][0] = fmaxf(v0 ? sc[nt][0] : -1e30f, v1 ? sc[nt][2] : -1e30f);
                px[nt][1] = fmaxf(v0 ? sc[nt][1] : -1e30f, v1 ? sc[nt][3] : -1e30f);
            }
#pragma unroll
            for (int off = 4; off < 32; off <<= 1)
#pragma unroll
                for (int nt = 0; nt < 4; ++nt) {
                    px[nt][0] = fmaxf(px[nt][0], __shfl_xor_sync(~0u, px[nt][0], off));
                    px[nt][1] = fmaxf(px[nt][1], __shfl_xor_sync(~0u, px[nt][1], off));
                }
            if (lane < 4) {
#pragma unroll
                for (int nt = 0; nt < 4; ++nt) {
                    int col = ng * 32 + nt * 8 + lane * 2;
                    S->pm[strip][col]     = px[nt][0];
                    S->pm[strip][col + 1] = px[nt][1];
                }
            }
        }
        __syncthreads();      // all warps done with GEMM1 (K buffer now dead)

        // prefetch K_{t+1} overlapping softmax part 2 + GEMM2
        if (t + 1 < NKT) issue_K(t + 1);

        if (tid < 64) {
            float mold = S->m[tid];
            float mx = fmaxf(fmaxf(S->pm[0][tid], S->pm[1][tid]),
                             fmaxf(S->pm[2][tid], S->pm[3][tid]));
            float mnew = fmaxf(mold, mx);
            S->m[tid] = mnew;
            S->r[tid] = __expf(mold - mnew);
        }
        __syncthreads();

        // ---- softmax part 2: exponentials -> P, partial sums ----
        {
            float pssum[4][2];
#pragma unroll
            for (int nt = 0; nt < 4; ++nt) {
                int col = ng * 32 + nt * 8 + cpair;
                float m0 = S->m[col], m1 = S->m[col + 1];
                float e00 = v0 ? __expf(sc[nt][0] - m0) : 0.f;
                float e01 = v0 ? __expf(sc[nt][1] - m1) : 0.f;
                float e10 = v1 ? __expf(sc[nt][2] - m0) : 0.f;
                float e11 = v1 ? __expf(sc[nt][3] - m1) : 0.f;
                S->P[col * 72 + r0]       = __float2half_rn(e00);
                S->P[(col + 1) * 72 + r0] = __float2half_rn(e01);
                S->P[col * 72 + r1]       = __float2half_rn(e10);
                S->P[(col + 1) * 72 + r1] = __float2half_rn(e11);
                pssum[nt][0] = e00 + e10;
                pssum[nt][1] = e01 + e11;
            }
#pragma unroll
            for (int off = 4; off < 32; off <<= 1)
#pragma unroll
                for (int nt = 0; nt < 4; ++nt) {
                    pssum[nt][0] += __shfl_xor_sync(~0u, pssum[nt][0], off);
                    pssum[nt][1] += __shfl_xor_sync(~0u, pssum[nt][1], off);
                }
            if (lane < 4) {
#pragma unroll
                for (int nt = 0; nt < 4; ++nt) {
                    int col = ng * 32 + nt * 8 + lane * 2;
                    S->ps[strip][col]     = pssum[nt][0];
                    S->ps[strip][col + 1] = pssum[nt][1];
                }
            }
        }
        // wait for V_t: groups outstanding are [V_t, K_{t+1}] (commit order) or [V_t] on last iter
        if (t + 1 < NKT) { CP_WAIT1(); } else { CP_WAIT0(); }
        __syncthreads();

        if (tid < 64) {
            S->l[tid] = S->l[tid] * S->r[tid]
                      + ((S->ps[0][tid] + S->ps[1][tid]) + (S->ps[2][tid] + S->ps[3][tid]));
        }

        // ---- GEMM2: rescale + accumulate ----
#pragma unroll
        for (int i = 0; i < 16; ++i) {
            int col = (i & 7) * 8 + cpair;
            float rv0 = S->r[col], rv1 = S->r[col + 1];
            acc[i][0] *= rv0; acc[i][1] *= rv1;
            acc[i][2] *= rv0; acc[i][3] *= rv1;
        }
#pragma unroll
        for (int kc = 0; kc < 64; kc += 16) {
            uint32_t pb4[4][4];
#pragma unroll
            for (int dn = 0; dn < 4; ++dn)
                ldsm_x4(pb4[dn], bP4 + dn * 16 * 72 * 2 + kc * 2);
#pragma unroll
            for (int s2 = 0; s2 < 2; ++s2) {
                uint32_t vh[4], vl[4];
                ldsm_x4(vh, aVh + s2 * 2304 + kc * 2);
                ldsm_x4(vl, aVl + s2 * 2304 + kc * 2);
#pragma unroll
                for (int nt = 0; nt < 8; ++nt) {
                    const uint32_t* pb = &pb4[nt >> 1][(nt & 1) * 2];
                    mma_f16(acc[s2 * 8 + nt], vh, pb);
                    mma_f16(acc[s2 * 8 + nt], vl, pb);
                }
            }
        }
        __syncthreads();      // all warps done with V_t (V buffer now dead)

        // prefetch V_{t+1} overlapping next GEMM1 + softmax part 1
        if (t + 1 < NKT) issue_V(t + 1);
    }

    // ---- epilogue ----
#pragma unroll
    for (int i = 0; i < 16; ++i) {
        int s2 = i >> 3, nt = i & 7;
        int col = nt * 8 + cpair;
        float li0 = 1.f / S->l[col], li1 = 1.f / S->l[col + 1];
        int row = wid * 32 + s2 * 16 + (lane >> 2);
        size_t o0 = ((size_t)(b * CH + row)) * NQ + q0 + col;
        size_t o1 = ((size_t)(b * CH + row + 8)) * NQ + q0 + col;
        out[o0]     = acc[i][0] * li0;
        out[o0 + 1] = acc[i][1] * li1;
        out[o1]     = acc[i][2] * li0;
        out[o1 + 1] = acc[i][3] * li1;
    }
}

// =================================================================
extern "C" void kernel_launch(void* const* d_in, const int* in_sizes, int n_in,
                              void* d_out, int out_size)
{
    (void)in_sizes; (void)n_in; (void)out_size;
    const float* x     = (const float*)d_in[0];
    const float* Wq    = (const float*)d_in[1];
    const float* bq    = (const float*)d_in[2];
    const float* gq    = (const float*)d_in[3];
    const float* betaq = (const float*)d_in[4];
    const float* Wk    = (const float*)d_in[5];
    const float* bk    = (const float*)d_in[6];
    const float* gk    = (const float*)d_in[7];
    const float* betak = (const float*)d_in[8];
    const float* Wv    = (const float*)d_in[9];
    const float* bv    = (const float*)d_in[10];
    const float* gv    = (const float*)d_in[11];
    const float* betav = (const float*)d_in[12];
    float* out = (float*)d_out;

    fused_conv_kernel<<<dim3(8, 64, BATCH), 256>>>(x, Wq, bq, Wk, Wv, bk, bv);
    bn_stats_kernel<<<dim3(CH, 3), 256>>>(gq, betaq, gk, betak, gv, betav);
    fused_convert_kernel<<<dim3(NKP / 32, 17, BATCH), 256>>>();

    cudaFuncSetAttribute(flash_mma_kernel,
                         cudaFuncAttributeMaxDynamicSharedMemorySize,
                         (int)sizeof(FS));
    flash_mma_kernel<<<dim3(NQ / 64, BATCH), 256, sizeof(FS)>>>(out);
}